// round 8
// baseline (speedup 1.0000x reference)
#include <cuda_runtime.h>
#include <cuda_bf16.h>
#include <stdint.h>

#define B_ROWS 2048
#define DIM    512
#define VOCAB  100000
#define BM 64
#define BN 64
#define BK 32
#define NKT (DIM / BK)               /* 16 k-tiles */
#define NT ((VOCAB + BN - 1) / BN)   /* 1563 column tiles */

// ArcFace constants
#define C_COS_M  0.8775825618903728f
#define C_SIN_M  0.479425538604203f
#define C_MM     0.2397127693021015f
#define C_THRESH -0.8775825618903728f
#define C_S      64.0f

// SMEM stage layout (bytes): 4 arrays of [64][BK+8] bf16 = 64*40*2 = 5120 each
#define ARR_BYTES   5120
#define STAGE_BYTES (4 * ARR_BYTES)   /* 20480 */
#define OFF_AH 0
#define OFF_AL (1 * ARR_BYTES)
#define OFF_BH (2 * ARR_BYTES)
#define OFF_BL (3 * ARR_BYTES)

// ---------------- device scratch (static allocations only) ----------------
__device__ __nv_bfloat16 g_e_hi[(size_t)B_ROWS * DIM];
__device__ __nv_bfloat16 g_e_lo[(size_t)B_ROWS * DIM];
__device__ __nv_bfloat16 g_w_hi[(size_t)VOCAB * DIM];        // 102.4 MB
__device__ __nv_bfloat16 g_w_lo[(size_t)VOCAB * DIM];        // 102.4 MB
__device__ float g_partM[(size_t)B_ROWS * NT];               // 12.8 MB
__device__ float g_partS[(size_t)B_ROWS * NT];               // 12.8 MB
__device__ float g_labelLogit[B_ROWS];
__device__ float g_nll[B_ROWS];

__device__ __forceinline__ float neg_inf() { return __int_as_float(0xff800000); }

__device__ __forceinline__ void cp16(uint32_t dst, const void* src, int src_sz) {
    asm volatile("cp.async.cg.shared.global [%0], [%1], 16, %2;\n"
                 :: "r"(dst), "l"(src), "r"(src_sz));
}
__device__ __forceinline__ void cp_commit() {
    asm volatile("cp.async.commit_group;\n" ::);
}
template <int N>
__device__ __forceinline__ void cp_wait() {
    asm volatile("cp.async.wait_group %0;\n" :: "n"(N));
}

// -------- normalize rows (fp32 -> L2-normalized split bf16 hi+lo) ---------
__global__ __launch_bounds__(256) void normalize_rows(const float* __restrict__ src,
                                                      int rows, int to_w) {
    int row = blockIdx.x * 8 + (threadIdx.x >> 5);
    if (row >= rows) return;
    int lane = threadIdx.x & 31;
    const float4* p = (const float4*)src + (size_t)row * (DIM / 4);
    float4 v[4];
    float ss = 0.f;
#pragma unroll
    for (int i = 0; i < 4; i++) {
        v[i] = p[lane + i * 32];
        ss += v[i].x * v[i].x + v[i].y * v[i].y + v[i].z * v[i].z + v[i].w * v[i].w;
    }
#pragma unroll
    for (int o = 16; o; o >>= 1) ss += __shfl_xor_sync(0xffffffffu, ss, o);
    float sc = 1.0f / fmaxf(sqrtf(ss), 1e-12f);
    __nv_bfloat162* dhi = ((__nv_bfloat162*)(to_w ? g_w_hi : g_e_hi)) + (size_t)row * (DIM / 2);
    __nv_bfloat162* dlo = ((__nv_bfloat162*)(to_w ? g_w_lo : g_e_lo)) + (size_t)row * (DIM / 2);
#pragma unroll
    for (int i = 0; i < 4; i++) {
        int j = lane + i * 32;
        float f[4] = {v[i].x * sc, v[i].y * sc, v[i].z * sc, v[i].w * sc};
        __nv_bfloat16 h[4], l[4];
#pragma unroll
        for (int q = 0; q < 4; q++) {
            h[q] = __float2bfloat16_rn(f[q]);
            l[q] = __float2bfloat16_rn(f[q] - __bfloat162float(h[q]));
        }
        __nv_bfloat162 hh0; hh0.x = h[0]; hh0.y = h[1];
        __nv_bfloat162 hh1; hh1.x = h[2]; hh1.y = h[3];
        __nv_bfloat162 ll0; ll0.x = l[0]; ll0.y = l[1];
        __nv_bfloat162 ll1; ll1.x = l[2]; ll1.y = l[3];
        dhi[j * 2 + 0] = hh0; dhi[j * 2 + 1] = hh1;
        dlo[j * 2 + 0] = ll0; dlo[j * 2 + 1] = ll1;
    }
}

// ---------------- fused GEMM + ArcFace margin + partial softmax ----------
__device__ __forceinline__ float arcface_logit(float c) {
    c = fminf(fmaxf(c, -1.f), 1.f);
    float s2 = fminf(fmaxf(1.f - c * c, 0.f), 1.f);
    float sn = sqrtf(s2);
    float cm = c * C_COS_M - sn * C_SIN_M;
    if (!(c > C_THRESH)) cm = c - C_MM;
    return cm * C_S;
}

#define MMA_BF16(CPTR, A0, A1, A2, A3, B0, B1)                                  \
    asm volatile("mma.sync.aligned.m16n8k16.row.col.f32.bf16.bf16.f32 "         \
                 "{%0,%1,%2,%3}, {%4,%5,%6,%7}, {%8,%9}, {%0,%1,%2,%3};"        \
                 : "+f"((CPTR)[0]), "+f"((CPTR)[1]), "+f"((CPTR)[2]), "+f"((CPTR)[3]) \
                 : "r"(A0), "r"(A1), "r"(A2), "r"(A3), "r"(B0), "r"(B1))

__global__ __launch_bounds__(128) void arcface_gemm(const int* __restrict__ labels) {
    __shared__ __align__(16) char s_raw[2 * STAGE_BYTES];   // 40960 B; reused as Ls in epilogue
    __shared__ int s_label[BM];

    const int t    = threadIdx.x;
    const int warp = t >> 5, lane = t & 31;
    const int row0 = blockIdx.x * BM;   // x = row block (fast dim) -> B tile L2 reuse
    const int col0 = blockIdx.y * BN;   // y = vocab column tile
    const int wm = (warp >> 1) * 32;
    const int wn = (warp & 1) * 32;

    const uint32_t sbase = (uint32_t)__cvta_generic_to_shared(s_raw);

    if (t < BM) s_label[t] = labels[row0 + t];   // labels are int32 (JAX x64 disabled)

    float acc[2][4][4];
#pragma unroll
    for (int i = 0; i < 2; i++)
#pragma unroll
        for (int j = 0; j < 4; j++)
#pragma unroll
            for (int k = 0; k < 4; k++) acc[i][j][k] = 0.f;

    // per-thread load slots: idx = t + i*128; r = idx>>2 (0..63), c = (idx&3)*8
    const int r_ld0 = t >> 2, c_ld = (t & 3) * 8;
    const int r_ld1 = (t + 128) >> 2;

    // ---- issue load for k-tile kt into stage st ----
    auto issue_load = [&](int kt, int st) {
        uint32_t sb = sbase + st * STAGE_BYTES;
#pragma unroll
        for (int i = 0; i < 2; i++) {
            int r = i ? r_ld1 : r_ld0;
            uint32_t soff = (uint32_t)(r * 80 + c_ld * 2);
            size_t aoff = (size_t)(row0 + r) * DIM + kt * BK + c_ld;
            cp16(sb + OFF_AH + soff, &g_e_hi[aoff], 16);
            cp16(sb + OFF_AL + soff, &g_e_lo[aoff], 16);
            int gc = col0 + r;
            int ok = (gc < VOCAB) ? 16 : 0;
            size_t boff = (size_t)(gc < VOCAB ? gc : 0) * DIM + kt * BK + c_ld;
            cp16(sb + OFF_BH + soff, &g_w_hi[boff], ok);
            cp16(sb + OFF_BL + soff, &g_w_lo[boff], ok);
        }
        cp_commit();
    };

    issue_load(0, 0);

    for (int kt = 0; kt < NKT; kt++) {
        const int st = kt & 1;
        if (kt + 1 < NKT) issue_load(kt + 1, st ^ 1);
        if (kt + 1 < NKT) cp_wait<1>(); else cp_wait<0>();
        __syncthreads();

        char* stage = s_raw + st * STAGE_BYTES;
        __nv_bfloat16 (*AsH)[BK + 8] = (__nv_bfloat16(*)[BK + 8])(stage + OFF_AH);
        __nv_bfloat16 (*AsL)[BK + 8] = (__nv_bfloat16(*)[BK + 8])(stage + OFF_AL);
        __nv_bfloat16 (*BsH)[BK + 8] = (__nv_bfloat16(*)[BK + 8])(stage + OFF_BH);
        __nv_bfloat16 (*BsL)[BK + 8] = (__nv_bfloat16(*)[BK + 8])(stage + OFF_BL);

#pragma unroll
        for (int ks = 0; ks < 2; ks++) {
            uint32_t ah[2][4], al[2][4], bh[2][4], bl[2][4];
#pragma unroll
            for (int i = 0; i < 2; i++) {
                int r = wm + i * 16 + (lane & 15);
                int c = ks * 16 + ((lane >> 4) << 3);
                uint32_t adH = (uint32_t)__cvta_generic_to_shared(&AsH[r][c]);
                uint32_t adL = (uint32_t)__cvta_generic_to_shared(&AsL[r][c]);
                asm volatile("ldmatrix.sync.aligned.m8n8.x4.shared.b16 {%0,%1,%2,%3}, [%4];"
                             : "=r"(ah[i][0]), "=r"(ah[i][1]), "=r"(ah[i][2]), "=r"(ah[i][3])
                             : "r"(adH));
                asm volatile("ldmatrix.sync.aligned.m8n8.x4.shared.b16 {%0,%1,%2,%3}, [%4];"
                             : "=r"(al[i][0]), "=r"(al[i][1]), "=r"(al[i][2]), "=r"(al[i][3])
                             : "r"(adL));
            }
#pragma unroll
            for (int jj = 0; jj < 2; jj++) {
                int g = lane >> 3, rr = lane & 7;
                int r = wn + jj * 16 + ((g >> 1) << 3) + rr;
                int c = ks * 16 + ((g & 1) << 3);
                uint32_t adH = (uint32_t)__cvta_generic_to_shared(&BsH[r][c]);
                uint32_t adL = (uint32_t)__cvta_generic_to_shared(&BsL[r][c]);
                asm volatile("ldmatrix.sync.aligned.m8n8.x4.shared.b16 {%0,%1,%2,%3}, [%4];"
                             : "=r"(bh[jj][0]), "=r"(bh[jj][1]), "=r"(bh[jj][2]), "=r"(bh[jj][3])
                             : "r"(adH));
                asm volatile("ldmatrix.sync.aligned.m8n8.x4.shared.b16 {%0,%1,%2,%3}, [%4];"
                             : "=r"(bl[jj][0]), "=r"(bl[jj][1]), "=r"(bl[jj][2]), "=r"(bl[jj][3])
                             : "r"(adL));
            }
#pragma unroll
            for (int i = 0; i < 2; i++)
#pragma unroll
                for (int jj = 0; jj < 2; jj++) {
                    float* c0 = acc[i][jj * 2 + 0];
                    float* c1 = acc[i][jj * 2 + 1];
                    // hi*hi
                    MMA_BF16(c0, ah[i][0], ah[i][1], ah[i][2], ah[i][3], bh[jj][0], bh[jj][1]);
                    MMA_BF16(c1, ah[i][0], ah[i][1], ah[i][2], ah[i][3], bh[jj][2], bh[jj][3]);
                    // hi*lo
                    MMA_BF16(c0, ah[i][0], ah[i][1], ah[i][2], ah[i][3], bl[jj][0], bl[jj][1]);
                    MMA_BF16(c1, ah[i][0], ah[i][1], ah[i][2], ah[i][3], bl[jj][2], bl[jj][3]);
                    // lo*hi
                    MMA_BF16(c0, al[i][0], al[i][1], al[i][2], al[i][3], bh[jj][0], bh[jj][1]);
                    MMA_BF16(c1, al[i][0], al[i][1], al[i][2], al[i][3], bh[jj][2], bh[jj][3]);
                }
        }
        __syncthreads();
    }

    // -------- epilogue: margin, label capture, per-row partial (m, s) ------
    // Stage buffers are dead now; reuse s_raw as Ls[64][65] floats (16640 B).
    float (*Ls)[BN + 1] = (float(*)[BN + 1])s_raw;

#pragma unroll
    for (int i = 0; i < 2; i++)
#pragma unroll
        for (int j = 0; j < 4; j++) {
            int rl = wm + i * 16 + (lane >> 2);
            int cl = wn + j * 8 + ((lane & 3) << 1);
#pragma unroll
            for (int h = 0; h < 2; h++) {
                int r = rl + h * 8;
#pragma unroll
                for (int q = 0; q < 2; q++) {
                    int c  = cl + q;
                    int gc = col0 + c;
                    float lg;
                    if (gc < VOCAB) {
                        lg = arcface_logit(acc[i][j][h * 2 + q]);
                        if (s_label[r] == gc) g_labelLogit[row0 + r] = lg;
                    } else {
                        lg = neg_inf();
                    }
                    Ls[r][c] = lg;
                }
            }
        }
    __syncthreads();

    if (t < BM) {
        float m = neg_inf();
#pragma unroll 8
        for (int c = 0; c < BN; c++) m = fmaxf(m, Ls[t][c]);
        float s = 0.f;
#pragma unroll 8
        for (int c = 0; c < BN; c++) s += expf(Ls[t][c] - m);
        g_partM[(size_t)(row0 + t) * NT + blockIdx.y] = m;
        g_partS[(size_t)(row0 + t) * NT + blockIdx.y] = s;
    }
}

// ---------------- per-row logsumexp combine + nll -------------------------
__global__ __launch_bounds__(256) void row_lse() {
    int row = blockIdx.x;
    __shared__ float red[256];
    int tid = threadIdx.x;
    const float* pm = g_partM + (size_t)row * NT;
    const float* ps = g_partS + (size_t)row * NT;
    float m = neg_inf();
    for (int i = tid; i < NT; i += 256) m = fmaxf(m, pm[i]);
    red[tid] = m;
    __syncthreads();
    for (int o = 128; o; o >>= 1) {
        if (tid < o) red[tid] = fmaxf(red[tid], red[tid + o]);
        __syncthreads();
    }
    m = red[0];
    __syncthreads();
    float s = 0.f;
    for (int i = tid; i < NT; i += 256) s += ps[i] * expf(pm[i] - m);
    red[tid] = s;
    __syncthreads();
    for (int o = 128; o; o >>= 1) {
        if (tid < o) red[tid] += red[tid + o];
        __syncthreads();
    }
    if (tid == 0) g_nll[row] = m + logf(red[0]) - g_labelLogit[row];
}

// ---------------- final mean ----------------------------------------------
__global__ __launch_bounds__(256) void final_mean(float* __restrict__ out) {
    __shared__ float red[256];
    int tid = threadIdx.x;
    float s = 0.f;
    for (int i = tid; i < B_ROWS; i += 256) s += g_nll[i];
    red[tid] = s;
    __syncthreads();
    for (int o = 128; o; o >>= 1) {
        if (tid < o) red[tid] += red[tid + o];
        __syncthreads();
    }
    if (tid == 0) out[0] = red[0] / (float)B_ROWS;
}

// ---------------- launch ---------------------------------------------------
extern "C" void kernel_launch(void* const* d_in, const int* in_sizes, int n_in,
                              void* d_out, int out_size) {
    const float* emb    = (const float*)d_in[0];
    const int*   labels = (const int*)d_in[1];    // int32: JAX default (x64 disabled)
    const float* weight = (const float*)d_in[2];

    normalize_rows<<<B_ROWS / 8, 256>>>(emb, B_ROWS, 0);
    normalize_rows<<<(VOCAB + 7) / 8, 256>>>(weight, VOCAB, 1);

    dim3 grid(B_ROWS / BM, NT);   // x = row blocks (fast) -> weight tile L2 reuse
    arcface_gemm<<<grid, 128>>>(labels);

    row_lse<<<B_ROWS, 256>>>();
    final_mean<<<1, 256>>>((float*)d_out);
}

// round 12
// speedup vs baseline: 1.9073x; 1.9073x over previous
#include <cuda_runtime.h>
#include <cuda_bf16.h>
#include <stdint.h>

#define B_ROWS 2048
#define DIM    512
#define VOCAB  100000
#define BM 128
#define BN 64
#define BK 32
#define NKT (DIM / BK)               /* 16 k-tiles */
#define NT ((VOCAB + BN - 1) / BN)   /* 1563 column tiles */

// ArcFace constants
#define C_COS_M  0.8775825618903728f
#define C_SIN_M  0.479425538604203f
#define C_MM     0.2397127693021015f
#define C_THRESH -0.8775825618903728f
#define C_S      64.0f

// SMEM stage layout (bytes): A[128][40] bf16 = 10240, B[64][40] bf16 = 5120
#define A_BYTES     10240
#define B_BYTES     5120
#define STAGE_BYTES (A_BYTES + B_BYTES)   /* 15360 */
#define OFF_A 0
#define OFF_B A_BYTES
// epilogue Ls[128][65] floats = 33280 B  > 2*STAGE_BYTES(30720): size for max
#define SRAW_BYTES 33280

// ---------------- device scratch (static allocations only) ----------------
__device__ __nv_bfloat16 g_e[(size_t)B_ROWS * DIM];          // 2 MB (L2-resident)
__device__ __nv_bfloat16 g_w[(size_t)VOCAB * DIM];           // 102.4 MB
__device__ float g_partM[(size_t)B_ROWS * NT];               // 12.8 MB
__device__ float g_partS[(size_t)B_ROWS * NT];               // 12.8 MB
__device__ float g_labelLogit[B_ROWS];
__device__ float g_nll[B_ROWS];

__device__ __forceinline__ float neg_inf() { return __int_as_float(0xff800000); }

__device__ __forceinline__ void cp16(uint32_t dst, const void* src, int src_sz) {
    asm volatile("cp.async.cg.shared.global [%0], [%1], 16, %2;\n"
                 :: "r"(dst), "l"(src), "r"(src_sz));
}
__device__ __forceinline__ void cp_commit() {
    asm volatile("cp.async.commit_group;\n" ::);
}
template <int N>
__device__ __forceinline__ void cp_wait() {
    asm volatile("cp.async.wait_group %0;\n" :: "n"(N));
}

// -------- normalize rows (fp32 -> L2-normalized bf16) ---------------------
// NOTE: destination selected INSIDE device code — __device__ symbols must not
// be passed as kernel args from host (host sees only the shadow object; ATS
// makes the bogus stores "succeed" into host memory -> silent zeros on device).
__global__ __launch_bounds__(256) void normalize_rows(const float* __restrict__ src,
                                                      int rows, int to_w) {
    int row = blockIdx.x * 8 + (threadIdx.x >> 5);
    if (row >= rows) return;
    int lane = threadIdx.x & 31;
    const float4* p = (const float4*)src + (size_t)row * (DIM / 4);
    float4 v[4];
    float ss = 0.f;
#pragma unroll
    for (int i = 0; i < 4; i++) {
        v[i] = p[lane + i * 32];
        ss += v[i].x * v[i].x + v[i].y * v[i].y + v[i].z * v[i].z + v[i].w * v[i].w;
    }
#pragma unroll
    for (int o = 16; o; o >>= 1) ss += __shfl_xor_sync(0xffffffffu, ss, o);
    float sc = 1.0f / fmaxf(sqrtf(ss), 1e-12f);
    __nv_bfloat162* d = ((__nv_bfloat162*)(to_w ? g_w : g_e)) + (size_t)row * (DIM / 2);
#pragma unroll
    for (int i = 0; i < 4; i++) {
        int j = lane + i * 32;
        d[j * 2 + 0] = __floats2bfloat162_rn(v[i].x * sc, v[i].y * sc);
        d[j * 2 + 1] = __floats2bfloat162_rn(v[i].z * sc, v[i].w * sc);
    }
}

// ---------------- fused GEMM + ArcFace margin + partial softmax ----------
__device__ __forceinline__ float arcface_logit(float c) {
    c = fminf(fmaxf(c, -1.f), 1.f);
    float s2 = fminf(fmaxf(1.f - c * c, 0.f), 1.f);
    float sn = sqrtf(s2);
    float cm = c * C_COS_M - sn * C_SIN_M;
    if (!(c > C_THRESH)) cm = c - C_MM;
    return cm * C_S;
}

#define MMA_BF16(CPTR, A0, A1, A2, A3, B0, B1)                                  \
    asm volatile("mma.sync.aligned.m16n8k16.row.col.f32.bf16.bf16.f32 "         \
                 "{%0,%1,%2,%3}, {%4,%5,%6,%7}, {%8,%9}, {%0,%1,%2,%3};"        \
                 : "+f"((CPTR)[0]), "+f"((CPTR)[1]), "+f"((CPTR)[2]), "+f"((CPTR)[3]) \
                 : "r"(A0), "r"(A1), "r"(A2), "r"(A3), "r"(B0), "r"(B1))

__global__ __launch_bounds__(256) void arcface_gemm(const int* __restrict__ labels) {
    __shared__ __align__(16) char s_raw[SRAW_BYTES];   // stages; reused as Ls in epilogue
    __shared__ int s_label[BM];

    const int t    = threadIdx.x;
    const int warp = t >> 5, lane = t & 31;
    const int row0 = blockIdx.x * BM;   // x = row block (fast dim) -> B tile L2 reuse
    const int col0 = blockIdx.y * BN;   // y = vocab column tile
    const int wm = (warp >> 1) * 32;    // 0,0,32,32,64,64,96,96
    const int wn = (warp & 1) * 32;     // 0,32 alternating

    const uint32_t sbase = (uint32_t)__cvta_generic_to_shared(s_raw);

    if (t < BM) s_label[t] = labels[row0 + t];   // labels are int32 (JAX x64 disabled)

    float acc[2][4][4];
#pragma unroll
    for (int i = 0; i < 2; i++)
#pragma unroll
        for (int j = 0; j < 4; j++)
#pragma unroll
            for (int k = 0; k < 4; k++) acc[i][j][k] = 0.f;

    // ---- issue load for k-tile kt into stage st ----
    // A tile: 128 rows x 32 cols bf16 = 512 x 16B chunks; 256 thr -> 2 each
    // B tile:  64 rows x 32 cols bf16 = 256 x 16B chunks; 256 thr -> 1 each
    auto issue_load = [&](int kt, int st) {
        uint32_t sb = sbase + st * STAGE_BYTES;
#pragma unroll
        for (int i = 0; i < 2; i++) {
            int idx = t + i * 256;
            int r = idx >> 2, c = (idx & 3) * 8;
            size_t aoff = (size_t)(row0 + r) * DIM + kt * BK + c;
            cp16(sb + OFF_A + (uint32_t)(r * 80 + c * 2), &g_e[aoff], 16);
        }
        {
            int r = t >> 2, c = (t & 3) * 8;
            int gc = col0 + r;
            int ok = (gc < VOCAB) ? 16 : 0;
            size_t boff = (size_t)(gc < VOCAB ? gc : 0) * DIM + kt * BK + c;
            cp16(sb + OFF_B + (uint32_t)(r * 80 + c * 2), &g_w[boff], ok);
        }
        cp_commit();
    };

    issue_load(0, 0);

    for (int kt = 0; kt < NKT; kt++) {
        const int st = kt & 1;
        if (kt + 1 < NKT) issue_load(kt + 1, st ^ 1);
        if (kt + 1 < NKT) cp_wait<1>(); else cp_wait<0>();
        __syncthreads();

        char* stage = s_raw + st * STAGE_BYTES;
        __nv_bfloat16 (*As)[BK + 8] = (__nv_bfloat16(*)[BK + 8])(stage + OFF_A);
        __nv_bfloat16 (*Bs)[BK + 8] = (__nv_bfloat16(*)[BK + 8])(stage + OFF_B);

#pragma unroll
        for (int ks = 0; ks < 2; ks++) {
            uint32_t a[2][4], b[2][4];
#pragma unroll
            for (int i = 0; i < 2; i++) {
                int r = wm + i * 16 + (lane & 15);
                int c = ks * 16 + ((lane >> 4) << 3);
                uint32_t ad = (uint32_t)__cvta_generic_to_shared(&As[r][c]);
                asm volatile("ldmatrix.sync.aligned.m8n8.x4.shared.b16 {%0,%1,%2,%3}, [%4];"
                             : "=r"(a[i][0]), "=r"(a[i][1]), "=r"(a[i][2]), "=r"(a[i][3])
                             : "r"(ad));
            }
#pragma unroll
            for (int jj = 0; jj < 2; jj++) {
                int g = lane >> 3, rr = lane & 7;
                int r = wn + jj * 16 + ((g >> 1) << 3) + rr;
                int c = ks * 16 + ((g & 1) << 3);
                uint32_t ad = (uint32_t)__cvta_generic_to_shared(&Bs[r][c]);
                asm volatile("ldmatrix.sync.aligned.m8n8.x4.shared.b16 {%0,%1,%2,%3}, [%4];"
                             : "=r"(b[jj][0]), "=r"(b[jj][1]), "=r"(b[jj][2]), "=r"(b[jj][3])
                             : "r"(ad));
            }
#pragma unroll
            for (int i = 0; i < 2; i++)
#pragma unroll
                for (int jj = 0; jj < 2; jj++) {
                    MMA_BF16(acc[i][jj * 2 + 0], a[i][0], a[i][1], a[i][2], a[i][3],
                             b[jj][0], b[jj][1]);
                    MMA_BF16(acc[i][jj * 2 + 1], a[i][0], a[i][1], a[i][2], a[i][3],
                             b[jj][2], b[jj][3]);
                }
        }
        __syncthreads();
    }

    // -------- epilogue: margin, label capture, per-row partial (m, s) ------
    // Stage buffers are dead now; reuse s_raw as Ls[128][65] floats (33280 B).
    float (*Ls)[BN + 1] = (float(*)[BN + 1])s_raw;

#pragma unroll
    for (int i = 0; i < 2; i++)
#pragma unroll
        for (int j = 0; j < 4; j++) {
            int rl = wm + i * 16 + (lane >> 2);
            int cl = wn + j * 8 + ((lane & 3) << 1);
#pragma unroll
            for (int h = 0; h < 2; h++) {
                int r = rl + h * 8;
#pragma unroll
                for (int q = 0; q < 2; q++) {
                    int c  = cl + q;
                    int gc = col0 + c;
                    float lg;
                    if (gc < VOCAB) {
                        lg = arcface_logit(acc[i][j][h * 2 + q]);
                        if (s_label[r] == gc) g_labelLogit[row0 + r] = lg;
                    } else {
                        lg = neg_inf();
                    }
                    Ls[r][c] = lg;
                }
            }
        }
    __syncthreads();

    if (t < BM) {
        float m = neg_inf();
#pragma unroll 8
        for (int c = 0; c < BN; c++) m = fmaxf(m, Ls[t][c]);
        float s = 0.f;
#pragma unroll 8
        for (int c = 0; c < BN; c++) s += expf(Ls[t][c] - m);
        g_partM[(size_t)(row0 + t) * NT + blockIdx.y] = m;
        g_partS[(size_t)(row0 + t) * NT + blockIdx.y] = s;
    }
}

// ---------------- per-row logsumexp combine + nll -------------------------
__global__ __launch_bounds__(256) void row_lse() {
    int row = blockIdx.x;
    __shared__ float red[256];
    int tid = threadIdx.x;
    const float* pm = g_partM + (size_t)row * NT;
    const float* ps = g_partS + (size_t)row * NT;
    float m = neg_inf();
    for (int i = tid; i < NT; i += 256) m = fmaxf(m, pm[i]);
    red[tid] = m;
    __syncthreads();
    for (int o = 128; o; o >>= 1) {
        if (tid < o) red[tid] = fmaxf(red[tid], red[tid + o]);
        __syncthreads();
    }
    m = red[0];
    __syncthreads();
    float s = 0.f;
    for (int i = tid; i < NT; i += 256) s += ps[i] * expf(pm[i] - m);
    red[tid] = s;
    __syncthreads();
    for (int o = 128; o; o >>= 1) {
        if (tid < o) red[tid] += red[tid + o];
        __syncthreads();
    }
    if (tid == 0) g_nll[row] = m + logf(red[0]) - g_labelLogit[row];
}

// ---------------- final mean ----------------------------------------------
__global__ __launch_bounds__(256) void final_mean(float* __restrict__ out) {
    __shared__ float red[256];
    int tid = threadIdx.x;
    float s = 0.f;
    for (int i = tid; i < B_ROWS; i += 256) s += g_nll[i];
    red[tid] = s;
    __syncthreads();
    for (int o = 128; o; o >>= 1) {
        if (tid < o) red[tid] += red[tid + o];
        __syncthreads();
    }
    if (tid == 0) out[0] = red[0] / (float)B_ROWS;
}

// ---------------- launch ---------------------------------------------------
extern "C" void kernel_launch(void* const* d_in, const int* in_sizes, int n_in,
                              void* d_out, int out_size) {
    const float* emb    = (const float*)d_in[0];
    const int*   labels = (const int*)d_in[1];    // int32: JAX default (x64 disabled)
    const float* weight = (const float*)d_in[2];

    normalize_rows<<<B_ROWS / 8, 256>>>(emb, B_ROWS, 0);
    normalize_rows<<<(VOCAB + 7) / 8, 256>>>(weight, VOCAB, 1);

    dim3 grid(B_ROWS / BM, NT);   // x = row blocks (fast) -> weight tile L2 reuse
    arcface_gemm<<<grid, 256>>>(labels);

    row_lse<<<B_ROWS, 256>>>();
    final_mean<<<1, 256>>>((float*)d_out);
}

// round 15
// speedup vs baseline: 2.0315x; 1.0651x over previous
#include <cuda_runtime.h>
#include <cuda_bf16.h>
#include <stdint.h>

#define B_ROWS 2048
#define DIM    512
#define VOCAB  100000
#define BM 128
#define BN 128
#define BK 32
#define NKT (DIM / BK)               /* 16 k-tiles */
#define NT  ((VOCAB + BN - 1) / BN)  /* 782 column tiles (last partial: 32 cols) */

// ArcFace constants
#define C_COS_M  0.8775825618903728f
#define C_SIN_M  0.479425538604203f
#define C_MM     0.2397127693021015f
#define C_THRESH -0.8775825618903728f
#define C_S      64.0f

// SMEM stage: A[128][40] + B[128][40] bf16 = 10240 + 10240
#define TILE_BYTES  10240
#define STAGE_BYTES (2 * TILE_BYTES)
#define OFF_A 0
#define OFF_B TILE_BYTES

// ---------------- device scratch (static allocations only) ----------------
__device__ __nv_bfloat16 g_e[(size_t)B_ROWS * DIM];          // 2 MB (L2-resident)
__device__ __nv_bfloat16 g_w[(size_t)VOCAB * DIM];           // 102.4 MB
__device__ float2 g_part[(size_t)NT * B_ROWS];               // 12.8 MB [tile][row]
__device__ float2 g_part2[16 * B_ROWS];
__device__ float  g_labelLogit[B_ROWS];
__device__ float  g_nll[B_ROWS];

__device__ __forceinline__ float neg_inf() { return __int_as_float(0xff800000); }

__device__ __forceinline__ void cp16(uint32_t dst, const void* src, int src_sz) {
    asm volatile("cp.async.cg.shared.global [%0], [%1], 16, %2;\n"
                 :: "r"(dst), "l"(src), "r"(src_sz));
}
__device__ __forceinline__ void cp_commit() { asm volatile("cp.async.commit_group;\n" ::); }
template <int N> __device__ __forceinline__ void cp_wait() {
    asm volatile("cp.async.wait_group %0;\n" :: "n"(N));
}

// -------- normalize rows (fp32 -> L2-normalized bf16); dst picked device-side --------
__global__ __launch_bounds__(256) void normalize_rows(const float* __restrict__ src,
                                                      int rows, int to_w) {
    int row = blockIdx.x * 8 + (threadIdx.x >> 5);
    if (row >= rows) return;
    int lane = threadIdx.x & 31;
    const float4* p = (const float4*)src + (size_t)row * (DIM / 4);
    float4 v[4];
    float ss = 0.f;
#pragma unroll
    for (int i = 0; i < 4; i++) {
        v[i] = p[lane + i * 32];
        ss += v[i].x * v[i].x + v[i].y * v[i].y + v[i].z * v[i].z + v[i].w * v[i].w;
    }
#pragma unroll
    for (int o = 16; o; o >>= 1) ss += __shfl_xor_sync(0xffffffffu, ss, o);
    float sc = 1.0f / fmaxf(sqrtf(ss), 1e-12f);
    __nv_bfloat162* d = ((__nv_bfloat162*)(to_w ? g_w : g_e)) + (size_t)row * (DIM / 2);
#pragma unroll
    for (int i = 0; i < 4; i++) {
        int j = lane + i * 32;
        d[j * 2 + 0] = __floats2bfloat162_rn(v[i].x * sc, v[i].y * sc);
        d[j * 2 + 1] = __floats2bfloat162_rn(v[i].z * sc, v[i].w * sc);
    }
}

__device__ __forceinline__ float arcface_logit(float c) {
    c = fminf(fmaxf(c, -1.f), 1.f);
    float s2 = fminf(fmaxf(1.f - c * c, 0.f), 1.f);
    float sn = sqrtf(s2);
    float cm = c * C_COS_M - sn * C_SIN_M;
    if (!(c > C_THRESH)) cm = c - C_MM;
    return cm * C_S;
}

#define MMA_BF16(CPTR, A0, A1, A2, A3, B0, B1)                                  \
    asm volatile("mma.sync.aligned.m16n8k16.row.col.f32.bf16.bf16.f32 "         \
                 "{%0,%1,%2,%3}, {%4,%5,%6,%7}, {%8,%9}, {%0,%1,%2,%3};"        \
                 : "+f"((CPTR)[0]), "+f"((CPTR)[1]), "+f"((CPTR)[2]), "+f"((CPTR)[3]) \
                 : "r"(A0), "r"(A1), "r"(A2), "r"(A3), "r"(B0), "r"(B1))

__global__ __launch_bounds__(256, 2) void arcface_gemm(const int* __restrict__ labels) {
    __shared__ __align__(16) char s_raw[2 * STAGE_BYTES];   // 40960 B
    __shared__ float2 s_ms[BM][4];                          // per-row per-Nwarp (m, s)
    __shared__ int s_label[BM];

    const int t    = threadIdx.x;
    const int warp = t >> 5, lane = t & 31;
    const int row0 = blockIdx.x * BM;   // x = row block (fast) -> B tile L2 reuse
    const int col0 = blockIdx.y * BN;   // y = vocab column tile
    const int wm = (warp >> 2) * 64;    // 2 warp rows
    const int wn = (warp & 3) * 32;     // 4 warp cols

    const uint32_t sbase = (uint32_t)__cvta_generic_to_shared(s_raw);

    if (t < BM) s_label[t] = labels[row0 + t];   // int32 labels

    float acc[4][4][4];
#pragma unroll
    for (int i = 0; i < 4; i++)
#pragma unroll
        for (int j = 0; j < 4; j++)
#pragma unroll
            for (int k = 0; k < 4; k++) acc[i][j][k] = 0.f;

    // ---- loads: A 128x32 (512 chunks, 2/thr), B 128x32 (512 chunks, 2/thr) ----
    auto issue_load = [&](int kt, int st) {
        uint32_t sb = sbase + st * STAGE_BYTES;
#pragma unroll
        for (int i = 0; i < 2; i++) {
            int idx = t + i * 256;
            int r = idx >> 2, c = (idx & 3) * 8;
            uint32_t soff = (uint32_t)(r * 80 + c * 2);
            cp16(sb + OFF_A + soff, &g_e[(size_t)(row0 + r) * DIM + kt * BK + c], 16);
            int gc = col0 + r;
            int ok = (gc < VOCAB) ? 16 : 0;
            cp16(sb + OFF_B + soff,
                 &g_w[(size_t)(gc < VOCAB ? gc : 0) * DIM + kt * BK + c], ok);
        }
        cp_commit();
    };

    issue_load(0, 0);

    for (int kt = 0; kt < NKT; kt++) {
        const int st = kt & 1;
        if (kt + 1 < NKT) issue_load(kt + 1, st ^ 1);
        if (kt + 1 < NKT) cp_wait<1>(); else cp_wait<0>();
        __syncthreads();

        char* stage = s_raw + st * STAGE_BYTES;
        __nv_bfloat16 (*As)[BK + 8] = (__nv_bfloat16(*)[BK + 8])(stage + OFF_A);
        __nv_bfloat16 (*Bs)[BK + 8] = (__nv_bfloat16(*)[BK + 8])(stage + OFF_B);

#pragma unroll
        for (int ks = 0; ks < 2; ks++) {
            uint32_t a[4][4], b[2][4];
#pragma unroll
            for (int i = 0; i < 4; i++) {
                int r = wm + i * 16 + (lane & 15);
                int c = ks * 16 + ((lane >> 4) << 3);
                uint32_t ad = (uint32_t)__cvta_generic_to_shared(&As[r][c]);
                asm volatile("ldmatrix.sync.aligned.m8n8.x4.shared.b16 {%0,%1,%2,%3}, [%4];"
                             : "=r"(a[i][0]), "=r"(a[i][1]), "=r"(a[i][2]), "=r"(a[i][3])
                             : "r"(ad));
            }
#pragma unroll
            for (int jj = 0; jj < 2; jj++) {
                int g = lane >> 3, rr = lane & 7;
                int r = wn + jj * 16 + ((g >> 1) << 3) + rr;
                int c = ks * 16 + ((g & 1) << 3);
                uint32_t ad = (uint32_t)__cvta_generic_to_shared(&Bs[r][c]);
                asm volatile("ldmatrix.sync.aligned.m8n8.x4.shared.b16 {%0,%1,%2,%3}, [%4];"
                             : "=r"(b[jj][0]), "=r"(b[jj][1]), "=r"(b[jj][2]), "=r"(b[jj][3])
                             : "r"(ad));
            }
#pragma unroll
            for (int i = 0; i < 4; i++)
#pragma unroll
                for (int j = 0; j < 4; j++)
                    MMA_BF16(acc[i][j], a[i][0], a[i][1], a[i][2], a[i][3],
                             b[j >> 1][(j & 1) * 2], b[j >> 1][(j & 1) * 2 + 1]);
        }
        __syncthreads();
    }

    // -------- epilogue: in-place margin on fragments + quad-shfl row reduce ----
    const bool full_tile = (col0 + BN <= VOCAB);
#pragma unroll
    for (int i = 0; i < 4; i++) {
        int rbase = wm + i * 16 + (lane >> 2);
#pragma unroll
        for (int h = 0; h < 2; h++) {
            int r = rbase + h * 8;
            int lbl = s_label[r];
#pragma unroll
            for (int j = 0; j < 4; j++)
#pragma unroll
                for (int q = 0; q < 2; q++) {
                    int gc = col0 + wn + j * 8 + ((lane & 3) << 1) + q;
                    float lg;
                    if (full_tile || gc < VOCAB) {
                        lg = arcface_logit(acc[i][j][h * 2 + q]);
                        if (gc == lbl) g_labelLogit[row0 + r] = lg;
                    } else {
                        lg = neg_inf();
                    }
                    acc[i][j][h * 2 + q] = lg;
                }
            // row max over this thread's 8 cols, then over the lane quad
            float mx = neg_inf();
#pragma unroll
            for (int j = 0; j < 4; j++)
#pragma unroll
                for (int q = 0; q < 2; q++) mx = fmaxf(mx, acc[i][j][h * 2 + q]);
            mx = fmaxf(mx, __shfl_xor_sync(0xffffffffu, mx, 1));
            mx = fmaxf(mx, __shfl_xor_sync(0xffffffffu, mx, 2));
            float ss = 0.f;
            if (mx != neg_inf()) {
#pragma unroll
                for (int j = 0; j < 4; j++)
#pragma unroll
                    for (int q = 0; q < 2; q++) {
                        float v = acc[i][j][h * 2 + q];
                        if (v != neg_inf()) ss += expf(v - mx);
                    }
            }
            ss += __shfl_xor_sync(0xffffffffu, ss, 1);
            ss += __shfl_xor_sync(0xffffffffu, ss, 2);
            if ((lane & 3) == 0) s_ms[r][warp & 3] = make_float2(mx, ss);
        }
    }
    __syncthreads();

    if (t < BM) {
        float m = neg_inf(), s = 0.f;
#pragma unroll
        for (int w = 0; w < 4; w++) {
            float2 p = s_ms[t][w];
            if (p.x == neg_inf()) continue;
            if (p.x > m) { s = s * expf(m - p.x) + p.y; m = p.x; }
            else         { s += p.y * expf(p.x - m); }
        }
        g_part[(size_t)blockIdx.y * B_ROWS + row0 + t] = make_float2(m, s);
    }
}

// ---------------- two-stage coalesced LSE combine ----------------
#define CHUNK 49   /* 16 * 49 >= 782 */
__global__ __launch_bounds__(256) void row_lse1() {
    int grow = blockIdx.x * 256 + threadIdx.x;   // grid.x = 8
    int c = blockIdx.y;                          // 0..15
    int t0 = c * CHUNK, t1 = t0 + CHUNK;
    if (t1 > NT) t1 = NT;
    float m = neg_inf(), s = 0.f;
    for (int n = t0; n < t1; n++) {
        float2 v = g_part[(size_t)n * B_ROWS + grow];
        if (v.x == neg_inf()) continue;
        if (v.x > m) { s = s * expf(m - v.x) + v.y; m = v.x; }
        else         { s += v.y * expf(v.x - m); }
    }
    g_part2[c * B_ROWS + grow] = make_float2(m, s);
}

__global__ __launch_bounds__(256) void row_lse2() {
    int grow = blockIdx.x * 256 + threadIdx.x;   // grid = 8
    float m = neg_inf(), s = 0.f;
#pragma unroll
    for (int c = 0; c < 16; c++) {
        float2 v = g_part2[c * B_ROWS + grow];
        if (v.x == neg_inf()) continue;
        if (v.x > m) { s = s * expf(m - v.x) + v.y; m = v.x; }
        else         { s += v.y * expf(v.x - m); }
    }
    g_nll[grow] = m + logf(s) - g_labelLogit[grow];
}

__global__ __launch_bounds__(256) void final_mean(float* __restrict__ out) {
    __shared__ float red[256];
    int tid = threadIdx.x;
    float s = 0.f;
    for (int i = tid; i < B_ROWS; i += 256) s += g_nll[i];
    red[tid] = s;
    __syncthreads();
    for (int o = 128; o; o >>= 1) {
        if (tid < o) red[tid] += red[tid + o];
        __syncthreads();
    }
    if (tid == 0) out[0] = red[0] / (float)B_ROWS;
}

// ---------------- launch ---------------------------------------------------
extern "C" void kernel_launch(void* const* d_in, const int* in_sizes, int n_in,
                              void* d_out, int out_size) {
    const float* emb    = (const float*)d_in[0];
    const int*   labels = (const int*)d_in[1];    // int32: JAX default (x64 disabled)
    const float* weight = (const float*)d_in[2];

    normalize_rows<<<B_ROWS / 8, 256>>>(emb, B_ROWS, 0);
    normalize_rows<<<(VOCAB + 7) / 8, 256>>>(weight, VOCAB, 1);

    dim3 grid(B_ROWS / BM, NT);   // x = row blocks (fast) -> weight tile L2 reuse
    arcface_gemm<<<grid, 256>>>(labels);

    row_lse1<<<dim3(B_ROWS / 256, 16), 256>>>();
    row_lse2<<<B_ROWS / 256, 256>>>();
    final_mean<<<1, 256>>>((float*)d_out);
}